// round 12
// baseline (speedup 1.0000x reference)
#include <cuda_runtime.h>
#include <cuda_bf16.h>

// Shapes (fixed by the problem)
#define B_   32
#define D_   512
#define HID_ 256
#define NF_  8
#define CIN_ 64
#define COUT_ 64
#define HW_  64

// Conv tiling: block = 16 oc x (32w x 8h) tile, 256 threads, 3 CTAs/SM.
// f32x2 lanes = (even ci, odd ci) partial sums -> summed in epilogue.
// thread = 4 oc x 4 px  (16 float2 accumulators = 32 regs)
#define OG_    16               // output channels per block
#define TW_    32               // tile width
#define TH_    8                // tile height
#define RH_    (TH_ + 2)        // staged rows incl. halo = 10
#define CP_    4                // ci-PAIRS per staged chunk (8 ci)
#define NCH_   (CIN_ / (2 * CP_))   // 8 chunks
#define ISTR2_ 72               // input row stride (34 col-pairs = 68 used, pad 72)
#define WROW_  36               // weight row stride per (cp,tap): 16 oc x 2 + pad (144B)

#define W_S_FLOATS    (32 * 9 * WROW_)         // 10368
#define IN_BUF_FLOATS (CP_ * RH_ * ISTR2_)     // 2880
#define SMEM_FLOATS   (W_S_FLOATS + 2 * IN_BUF_FLOATS)  // 16128 -> 64512 B

// -------- device scratch (no allocations allowed) --------
__device__ float g_attn[B_ * NF_];
__device__ float g_h[B_ * HID_];
__device__ float g_aggw[B_ * COUT_ * CIN_ * 9];  // [b][oc][ci][tap], 4.7 MB

// -------- packed fp32x2 FMA (sm_100+ PTX) --------
__device__ __forceinline__ void fma2(float2& c, const float2 a, const float2 b) {
    asm("fma.rn.f32x2 %0, %1, %2, %0;"
        : "+l"(reinterpret_cast<unsigned long long&>(c))
        : "l"(reinterpret_cast<const unsigned long long&>(a)),
          "l"(reinterpret_cast<const unsigned long long&>(b)));
}

struct __align__(16) f2x2 { float2 a, b; };   // one LDS.128 = two f32x2 operands

// ============================================================
// Kernel 1a: fc1 -> relu -> g_h.   grid(32, 8), block 256.
// ============================================================
__global__ void fc1_kernel(const float* __restrict__ x,
                           const float* __restrict__ w1, const float* __restrict__ b1)
{
    const int b = blockIdx.x, s = blockIdx.y, t = threadIdx.x;
    __shared__ __align__(16) float xs[D_];
    for (int i = t; i < D_; i += 256) xs[i] = x[b * D_ + i];
    __syncthreads();

    const int u = s * 32 + (t >> 3);
    const int l8 = t & 7;
    const float4* wr = reinterpret_cast<const float4*>(w1 + (size_t)u * D_);
    const float4* xv = reinterpret_cast<const float4*>(xs);
    float acc = 0.f;
#pragma unroll
    for (int i = 0; i < 16; i++) {
        float4 w4 = wr[l8 + 8 * i], x4 = xv[l8 + 8 * i];
        acc += w4.x * x4.x + w4.y * x4.y + w4.z * x4.z + w4.w * x4.w;
    }
#pragma unroll
    for (int o = 4; o > 0; o >>= 1) acc += __shfl_xor_sync(0xffffffffu, acc, o);
    if (l8 == 0) g_h[b * HID_ + u] = fmaxf(acc + b1[u], 0.f);
}

// ============================================================
// Kernel 1b: fc2 + softmax -> g_attn (+ tuple tail of d_out). grid(32), block 256.
// ============================================================
__global__ void fc2_kernel(const float* __restrict__ w2, const float* __restrict__ b2,
                           float* __restrict__ attn_out, int write_out)
{
    const int b = blockIdx.x, t = threadIdx.x;
    __shared__ float hs[HID_];
    __shared__ float ls[NF_];
    __shared__ float as_[NF_];
    hs[t] = g_h[b * HID_ + t];
    __syncthreads();

    const int f = t >> 5, lane = t & 31;
    float s = 0.f;
#pragma unroll
    for (int i = 0; i < HID_ / 32; i++) s += hs[lane + 32 * i] * w2[f * HID_ + lane + 32 * i];
#pragma unroll
    for (int o = 16; o > 0; o >>= 1) s += __shfl_xor_sync(0xffffffffu, s, o);
    if (lane == 0) ls[f] = s + b2[f];
    __syncthreads();

    if (t == 0) {
        float m = -1e30f;
#pragma unroll
        for (int i = 0; i < NF_; i++) m = fmaxf(m, ls[i]);
        float Z = 0.f, e[NF_];
#pragma unroll
        for (int i = 0; i < NF_; i++) { e[i] = expf((ls[i] - m) * (1.0f / 30.0f)); Z += e[i]; }
#pragma unroll
        for (int i = 0; i < NF_; i++) as_[i] = e[i] / Z;
    }
    __syncthreads();
    if (t < NF_) {
        g_attn[b * NF_ + t] = as_[t];
        if (write_out) attn_out[b * NF_ + t] = as_[t];
    }
}

// ============================================================
// Kernel 2: agg_w[b] = sum_f attn[b,f] * W[f]   (float4 streamed)
// ============================================================
__global__ void agg_kernel(const float* __restrict__ weight)
{
    const int b = blockIdx.y;
    const int e = blockIdx.x * blockDim.x + threadIdx.x;
    __shared__ float a[NF_];
    if (threadIdx.x < NF_) a[threadIdx.x] = g_attn[b * NF_ + threadIdx.x];
    __syncthreads();

    const float4* W = reinterpret_cast<const float4*>(weight);
    float4 acc = make_float4(0.f, 0.f, 0.f, 0.f);
#pragma unroll
    for (int f = 0; f < NF_; f++) {
        float4 w = W[(size_t)f * 9216 + e];
        float af = a[f];
        acc.x += af * w.x; acc.y += af * w.y; acc.z += af * w.z; acc.w += af * w.w;
    }
    reinterpret_cast<float4*>(g_aggw)[(size_t)b * 9216 + e] = acc;
}

// ============================================================
// Kernel 3 staging: CP_ ci-pairs, RH_ rows x 34 cols, channel-interleaved float2.
// ============================================================
__device__ __forceinline__ void stage_chunk(
    float* __restrict__ buf, const float* __restrict__ xin,
    int cpb, int tile_x, int tile_y, int t)
{
    for (int idx = t; idx < CP_ * RH_ * 34; idx += 256) {
        int cp  = idx / (RH_ * 34);
        int rem = idx - cp * (RH_ * 34);
        int r = rem / 34;
        int c = rem - r * 34;
        int gy = tile_y - 1 + r, gx = tile_x - 1 + c;
        float v0 = 0.f, v1 = 0.f;
        if ((unsigned)gy < (unsigned)HW_ && (unsigned)gx < (unsigned)HW_) {
            const float* p = xin + (size_t)(cpb + cp) * 2 * (HW_ * HW_) + gy * HW_ + gx;
            v0 = __ldg(p);
            v1 = __ldg(p + HW_ * HW_);
        }
        *reinterpret_cast<float2*>(&buf[(cp * RH_ + r) * ISTR2_ + 2 * c]) =
            make_float2(v0, v1);
    }
}

// ============================================================
// Kernel 3: per-sample 3x3 conv, pad 1. f32x2 over (even ci, odd ci).
// grid(16 tiles[32x8], 4 og, 32 b), block 256, 3 CTAs/SM.
// thread: oq = t>>6 (4 oc), trow = (t&63)>>3, x0 = (t&7)*4 (4 px).
// ============================================================
__global__ void __launch_bounds__(256, 3)
conv_kernel(const float* __restrict__ x, const float* __restrict__ bias_p,
            float* __restrict__ out)
{
    extern __shared__ float smem[];
    float* w_s = smem;                       // [cp32][tap9][oc16][2], row stride WROW_
    float* ib0 = smem + W_S_FLOATS;
    float* ib1 = ib0 + IN_BUF_FLOATS;

    const int b    = blockIdx.z;
    const int og   = blockIdx.y;               // 0..3
    const int tile = blockIdx.x;               // 0..15
    const int tile_y = (tile >> 1) * TH_;
    const int tile_x = (tile & 1) * TW_;
    const int t    = threadIdx.x;
    const int oq   = t >> 6;                   // 0..3 (4 oc each)
    const int pos  = t & 63;
    const int trow = pos >> 3;                 // 0..7
    const int x0   = (pos & 7) * 4;            // 0..28

    // prologue: weight slice -> [cp][tap][oc][2] smem (coalesced STS, scattered LDG)
    {
        const float* wg = g_aggw + ((size_t)b * COUT_ + og * OG_) * (CIN_ * 9);
        for (int idx = t; idx < 32 * 9 * 32; idx += 256) {
            int p    = idx & 1;
            int oc   = (idx >> 1) & 15;
            int tc   = idx >> 5;               // cp*9 + tap
            int cp   = tc / 9;
            int tap  = tc - cp * 9;
            w_s[tc * WROW_ + oc * 2 + p] =
                wg[(size_t)oc * (CIN_ * 9) + (2 * cp + p) * 9 + tap];
        }
    }

    float2 acc[4][4];                          // [oc][px], .x even ci / .y odd ci
#pragma unroll
    for (int o = 0; o < 4; o++)
#pragma unroll
        for (int j = 0; j < 4; j++) acc[o][j] = make_float2(0.f, 0.f);

    const float* xin = x + (size_t)b * CIN_ * HW_ * HW_;

    stage_chunk(ib0, xin, 0, tile_x, tile_y, t);
    __syncthreads();   // covers w_s + first chunk

    for (int ch = 0; ch < NCH_; ch++) {
        float* cur = (ch & 1) ? ib1 : ib0;
        float* nxt = (ch & 1) ? ib0 : ib1;
        if (ch + 1 < NCH_)
            stage_chunk(nxt, xin, (ch + 1) * CP_, tile_x, tile_y, t);

        const float* wch = w_s + (size_t)ch * (CP_ * 9) * WROW_ + oq * 8;
#pragma unroll
        for (int cp = 0; cp < CP_; cp++) {
            const float* ib = cur + (cp * RH_ + trow) * ISTR2_ + 2 * x0;
            const float* wc = wch + cp * 9 * WROW_;
#pragma unroll
            for (int ky = 0; ky < 3; ky++) {
                // 6 col-pairs via 3 LDS.128 (channel-interleaved, no packing MOVs)
                const f2x2* ip = reinterpret_cast<const f2x2*>(ib + ky * ISTR2_);
                f2x2 iA = ip[0], iB = ip[1], iC = ip[2];
                float2 iv[6] = { iA.a, iA.b, iB.a, iB.b, iC.a, iC.b };
#pragma unroll
                for (int kx = 0; kx < 3; kx++) {
                    // 4 oc weight pairs for this tap: 2 broadcast LDS.128
                    const f2x2* wp = reinterpret_cast<const f2x2*>(
                        wc + (ky * 3 + kx) * WROW_);
                    f2x2 w01 = wp[0], w23 = wp[1];
#pragma unroll
                    for (int j = 0; j < 4; j++) {
                        const float2 ix = iv[j + kx];
                        fma2(acc[0][j], w01.a, ix);
                        fma2(acc[1][j], w01.b, ix);
                        fma2(acc[2][j], w23.a, ix);
                        fma2(acc[3][j], w23.b, ix);
                    }
                }
            }
        }
        __syncthreads();   // nxt staged + cur free
    }

    // epilogue: combine even/odd halves + dynamic bias; float4 stores
    float at[NF_];
#pragma unroll
    for (int f = 0; f < NF_; f++) at[f] = g_attn[b * NF_ + f];
    const int gx0 = tile_x + x0, gy0 = tile_y + trow;
#pragma unroll
    for (int o = 0; o < 4; o++) {
        const int oc = og * OG_ + oq * 4 + o;
        float bias = 0.f;
#pragma unroll
        for (int f = 0; f < NF_; f++) bias += at[f] * bias_p[f * COUT_ + oc];
        float* op = out + (((size_t)b * COUT_ + oc) * HW_ + gy0) * HW_ + gx0;
        *reinterpret_cast<float4*>(op) = make_float4(
            acc[o][0].x + acc[o][0].y + bias,
            acc[o][1].x + acc[o][1].y + bias,
            acc[o][2].x + acc[o][2].y + bias,
            acc[o][3].x + acc[o][3].y + bias);
    }
}

// ============================================================
extern "C" void kernel_launch(void* const* d_in, const int* in_sizes, int n_in,
                              void* d_out, int out_size)
{
    const float* fc_in    = (const float*)d_in[0];  // [B, D]
    const float* model_in = (const float*)d_in[1];  // [B, CIN, HW, HW]
    const float* fc1_w    = (const float*)d_in[2];  // [HID, D]
    const float* fc1_b    = (const float*)d_in[3];  // [HID]
    const float* fc2_w    = (const float*)d_in[4];  // [NF, HID]
    const float* fc2_b    = (const float*)d_in[5];  // [NF]
    const float* weight   = (const float*)d_in[6];  // [NF, COUT, CIN, 3, 3]
    const float* bias_p   = (const float*)d_in[7];  // [NF, COUT]
    float* out = (float*)d_out;

    const int conv_elems = B_ * COUT_ * HW_ * HW_;        // 8388608
    const int attn_elems = B_ * NF_;                       // 256
    int write_attn = (out_size >= conv_elems + attn_elems) ? 1 : 0;
    float* attn_out = write_attn ? (out + conv_elems) : out;

    fc1_kernel<<<dim3(B_, 8), 256>>>(fc_in, fc1_w, fc1_b);
    fc2_kernel<<<B_, 256>>>(fc2_w, fc2_b, attn_out, write_attn);
    agg_kernel<<<dim3(36, B_), 256>>>(weight);

    const size_t smem_bytes = (size_t)SMEM_FLOATS * sizeof(float);  // 64512
    cudaFuncSetAttribute(conv_kernel, cudaFuncAttributeMaxDynamicSharedMemorySize,
                         (int)smem_bytes);
    conv_kernel<<<dim3(16, 4, B_), 256, smem_bytes>>>(model_in, bias_p, out);
}

// round 14
// speedup vs baseline: 1.7871x; 1.7871x over previous
#include <cuda_runtime.h>
#include <cuda_bf16.h>
#include <cstdint>

// Shapes (fixed by the problem)
#define B_   32
#define D_   512
#define HID_ 256
#define NF_  8
#define CIN_ 64
#define COUT_ 64
#define HW_  64

// Conv tiling: CTA = 1 sample x (32w x 8h px) x all 64 oc. 256 thr, 2 CTAs/SM.
// GEMM per tap: M=px (warp: m16 x2 tiles = its 32-px row), N=oc (8 n-tiles), K=ci.
#define CC_    8                 // ci per chunk
#define NCH_   (CIN_ / CC_)      // 8
#define IROW_  36                // input smem row stride (34 used)
#define IPL_   (10 * IROW_)      // ci plane stride = 360 (360%32=8 -> conflict-free)
#define WROW_  72                // weight smem row stride per (tap,ci): 64 oc + 8 pad

#define WBUF_  (9 * CC_ * WROW_)   // 5184 floats per buffer
#define IBUF_  (CC_ * IPL_)        // 2880 floats per buffer
#define SMEM_FLOATS (2 * WBUF_ + 2 * IBUF_)   // 16128 -> 64512 B

// -------- device scratch (no allocations allowed) --------
__device__ float g_attn[B_ * NF_];
__device__ float g_h[B_ * HID_];
// transposed + tf32-rounded aggregated weights: [b][tap9][ci64][oc64]
__device__ float g_aggw[B_ * 9 * CIN_ * COUT_];

// -------- helpers --------
__device__ __forceinline__ float tf32r(float x) {
    uint32_t u;
    asm("cvt.rna.tf32.f32 %0, %1;" : "=r"(u) : "f"(x));
    return __uint_as_float(u);
}

__device__ __forceinline__ void mma8(float4& d,
                                     float a0, float a1, float a2, float a3,
                                     float b0, float b1) {
    asm("mma.sync.aligned.m16n8k8.row.col.f32.tf32.tf32.f32 "
        "{%0,%1,%2,%3},{%4,%5,%6,%7},{%8,%9},{%0,%1,%2,%3};"
        : "+f"(d.x), "+f"(d.y), "+f"(d.z), "+f"(d.w)
        : "r"(__float_as_uint(a0)), "r"(__float_as_uint(a1)),
          "r"(__float_as_uint(a2)), "r"(__float_as_uint(a3)),
          "r"(__float_as_uint(b0)), "r"(__float_as_uint(b1)));
}

// ============================================================
// Kernel 1a: fc1 -> relu -> g_h.   grid(32, 8), block 256.
// ============================================================
__global__ void fc1_kernel(const float* __restrict__ x,
                           const float* __restrict__ w1, const float* __restrict__ b1)
{
    const int b = blockIdx.x, s = blockIdx.y, t = threadIdx.x;
    __shared__ __align__(16) float xs[D_];
    for (int i = t; i < D_; i += 256) xs[i] = x[b * D_ + i];
    __syncthreads();

    const int u = s * 32 + (t >> 3);
    const int l8 = t & 7;
    const float4* wr = reinterpret_cast<const float4*>(w1 + (size_t)u * D_);
    const float4* xv = reinterpret_cast<const float4*>(xs);
    float acc = 0.f;
#pragma unroll
    for (int i = 0; i < 16; i++) {
        float4 w4 = wr[l8 + 8 * i], x4 = xv[l8 + 8 * i];
        acc += w4.x * x4.x + w4.y * x4.y + w4.z * x4.z + w4.w * x4.w;
    }
#pragma unroll
    for (int o = 4; o > 0; o >>= 1) acc += __shfl_xor_sync(0xffffffffu, acc, o);
    if (l8 == 0) g_h[b * HID_ + u] = fmaxf(acc + b1[u], 0.f);
}

// ============================================================
// Kernel 1b: fc2 + softmax -> g_attn (+ tuple tail of d_out). grid(32), block 256.
// ============================================================
__global__ void fc2_kernel(const float* __restrict__ w2, const float* __restrict__ b2,
                           float* __restrict__ attn_out, int write_out)
{
    const int b = blockIdx.x, t = threadIdx.x;
    __shared__ float hs[HID_];
    __shared__ float ls[NF_];
    __shared__ float as_[NF_];
    hs[t] = g_h[b * HID_ + t];
    __syncthreads();

    const int f = t >> 5, lane = t & 31;
    float s = 0.f;
#pragma unroll
    for (int i = 0; i < HID_ / 32; i++) s += hs[lane + 32 * i] * w2[f * HID_ + lane + 32 * i];
#pragma unroll
    for (int o = 16; o > 0; o >>= 1) s += __shfl_xor_sync(0xffffffffu, s, o);
    if (lane == 0) ls[f] = s + b2[f];
    __syncthreads();

    if (t == 0) {
        float m = -1e30f;
#pragma unroll
        for (int i = 0; i < NF_; i++) m = fmaxf(m, ls[i]);
        float Z = 0.f, e[NF_];
#pragma unroll
        for (int i = 0; i < NF_; i++) { e[i] = expf((ls[i] - m) * (1.0f / 30.0f)); Z += e[i]; }
#pragma unroll
        for (int i = 0; i < NF_; i++) as_[i] = e[i] / Z;
    }
    __syncthreads();
    if (t < NF_) {
        g_attn[b * NF_ + t] = as_[t];
        if (write_out) attn_out[b * NF_ + t] = as_[t];
    }
}

// ============================================================
// Kernel 2: agg_w -> TRANSPOSED [b][tap][ci][oc] layout, tf32-rounded.
// grid(36, 32), block 256; reads weight [f][oc][ci][tap] linearly (float4).
// ============================================================
__global__ void agg_kernel(const float* __restrict__ weight)
{
    const int b = blockIdx.y;
    const int e = blockIdx.x * blockDim.x + threadIdx.x;  // float4 idx < 9216
    __shared__ float a[NF_];
    if (threadIdx.x < NF_) a[threadIdx.x] = g_attn[b * NF_ + threadIdx.x];
    __syncthreads();

    const float4* W = reinterpret_cast<const float4*>(weight);
    float4 acc = make_float4(0.f, 0.f, 0.f, 0.f);
#pragma unroll
    for (int f = 0; f < NF_; f++) {
        float4 w = W[(size_t)f * 9216 + e];
        float af = a[f];
        acc.x += af * w.x; acc.y += af * w.y; acc.z += af * w.z; acc.w += af * w.w;
    }
    float v[4] = { acc.x, acc.y, acc.z, acc.w };
    float* dst = g_aggw + (size_t)b * (9 * CIN_ * COUT_);
#pragma unroll
    for (int r = 0; r < 4; r++) {
        int idx = 4 * e + r;                 // oc*576 + ci*9 + tap
        int oc  = idx / 576;
        int rem = idx - oc * 576;
        int ci  = rem / 9;
        int tap = rem - ci * 9;
        dst[(tap * CIN_ + ci) * COUT_ + oc] = tf32r(v[r]);
    }
}

// ============================================================
// Conv staging
// ============================================================
__device__ __forceinline__ void stage_w(float* __restrict__ buf,
                                        const float* __restrict__ gw,
                                        int cb, int t)
{
    // dest [tap9][ci8][oc64] stride WROW_; src [tap][ci64][oc64] slice cb..cb+7
    for (int idx = t; idx < 9 * CC_ * 64; idx += 256) {
        int oc = idx & 63;
        int tc = idx >> 6;                 // tap*8 + ci
        int ci = tc & 7;
        int tap = tc >> 3;
        buf[tc * WROW_ + oc] = gw[(tap * CIN_ + cb + ci) * COUT_ + oc];
    }
}

__device__ __forceinline__ void stage_i(float* __restrict__ buf,
                                        const float* __restrict__ xin,
                                        int cb, int tile_x, int tile_y, int t)
{
    // CC_ ci planes x 10 rows x 34 cols, zero-padded halo, tf32-rounded
    for (int idx = t; idx < CC_ * 10 * 34; idx += 256) {
        int ci  = idx / 340;
        int rem = idx - ci * 340;
        int r = rem / 34;
        int c = rem - r * 34;
        int gy = tile_y - 1 + r, gx = tile_x - 1 + c;
        float v = 0.f;
        if ((unsigned)gy < (unsigned)HW_ && (unsigned)gx < (unsigned)HW_)
            v = __ldg(&xin[(size_t)(cb + ci) * (HW_ * HW_) + gy * HW_ + gx]);
        buf[ci * IPL_ + r * IROW_ + c] = tf32r(v);
    }
}

// ============================================================
// Kernel 3: tf32 tensor-core conv (9 shifted GEMMs), pad 1.
// grid(16 tiles[32x8], 32 b), block 256 (8 warps), 2 CTAs/SM.
// warp w owns spatial row w of the tile (2 m16 px-tiles), all 64 oc (8 n-tiles).
// ============================================================
__global__ void __launch_bounds__(256, 2)
conv_kernel(const float* __restrict__ x, const float* __restrict__ bias_p,
            float* __restrict__ out)
{
    extern __shared__ float smem[];
    float* wb[2] = { smem, smem + WBUF_ };
    float* ib[2] = { smem + 2 * WBUF_, smem + 2 * WBUF_ + IBUF_ };

    const int b    = blockIdx.y;
    const int tile = blockIdx.x;               // 0..15
    const int tile_y = (tile >> 1) * 8;
    const int tile_x = (tile & 1) * 32;
    const int t    = threadIdx.x;
    const int w    = t >> 5;                   // warp id = spatial row 0..7
    const int lane = t & 31;
    const int kl   = lane & 3;                 // k-lane (ci)
    const int nl   = lane >> 2;                // n/m lane

    const float* xin = x + (size_t)b * CIN_ * HW_ * HW_;
    const float* gw  = g_aggw + (size_t)b * (9 * CIN_ * COUT_);

    float4 acc[2][8];                          // [m-tile][n-tile(oc/8)]
#pragma unroll
    for (int m = 0; m < 2; m++)
#pragma unroll
        for (int j = 0; j < 8; j++) acc[m][j] = make_float4(0.f, 0.f, 0.f, 0.f);

    stage_w(wb[0], gw, 0, t);
    stage_i(ib[0], xin, 0, tile_x, tile_y, t);
    __syncthreads();

    for (int ch = 0; ch < NCH_; ch++) {
        const int cur = ch & 1;
        if (ch + 1 < NCH_) {
            stage_w(wb[1 - cur], gw, (ch + 1) * CC_, t);
            stage_i(ib[1 - cur], xin, (ch + 1) * CC_, tile_x, tile_y, t);
        }
        const float* I = ib[cur];
        const float* W = wb[cur];

#pragma unroll
        for (int tap = 0; tap < 9; tap++) {
            const int dy = tap / 3, dx = tap - 3 * (tap / 3);
            // A frags (input patches): a0 (px=nl, ci=kl), a1 (+8px), a2 (+4ci), a3 both
            const float* Ip = I + kl * IPL_ + (w + dy) * IROW_ + dx + nl;
            const float a00 = Ip[0],    a01 = Ip[8];
            const float a02 = Ip[4 * IPL_],       a03 = Ip[4 * IPL_ + 8];
            const float a10 = Ip[16],   a11 = Ip[24];
            const float a12 = Ip[4 * IPL_ + 16],  a13 = Ip[4 * IPL_ + 24];
            // B frags (weights): b0 (ci=kl, oc=8j+nl), b1 (ci=kl+4)
            const float* Wp = W + tap * (CC_ * WROW_) + kl * WROW_ + nl;
#pragma unroll
            for (int j = 0; j < 8; j++) {
                const float b0 = Wp[8 * j];
                const float b1 = Wp[8 * j + 4 * WROW_];
                mma8(acc[0][j], a00, a01, a02, a03, b0, b1);
                mma8(acc[1][j], a10, a11, a12, a13, b0, b1);
            }
        }
        __syncthreads();   // next buffers staged + cur free
    }

    // epilogue: dynamic bias (smem, reuses wb[0] space after final barrier)
    float* bias_s = smem;
    if (t < COUT_) {
        float bs = 0.f;
#pragma unroll
        for (int f = 0; f < NF_; f++) bs += g_attn[b * NF_ + f] * bias_p[f * COUT_ + t];
        bias_s[t] = bs;
    }
    __syncthreads();

    const int gy = tile_y + w;
#pragma unroll
    for (int mt = 0; mt < 2; mt++) {
        const int gxa = tile_x + mt * 16 + nl;
        const int gxb = gxa + 8;
#pragma unroll
        for (int j = 0; j < 8; j++) {
            const int oc0 = 8 * j + 2 * kl;
            const int oc1 = oc0 + 1;
            const float bs0 = bias_s[oc0], bs1 = bias_s[oc1];
            float* p0 = out + (((size_t)b * COUT_ + oc0) * HW_ + gy) * HW_;
            float* p1 = out + (((size_t)b * COUT_ + oc1) * HW_ + gy) * HW_;
            p0[gxa] = acc[mt][j].x + bs0;
            p1[gxa] = acc[mt][j].y + bs1;
            p0[gxb] = acc[mt][j].z + bs0;
            p1[gxb] = acc[mt][j].w + bs1;
        }
    }
}

// ============================================================
extern "C" void kernel_launch(void* const* d_in, const int* in_sizes, int n_in,
                              void* d_out, int out_size)
{
    const float* fc_in    = (const float*)d_in[0];  // [B, D]
    const float* model_in = (const float*)d_in[1];  // [B, CIN, HW, HW]
    const float* fc1_w    = (const float*)d_in[2];  // [HID, D]
    const float* fc1_b    = (const float*)d_in[3];  // [HID]
    const float* fc2_w    = (const float*)d_in[4];  // [NF, HID]
    const float* fc2_b    = (const float*)d_in[5];  // [NF]
    const float* weight   = (const float*)d_in[6];  // [NF, COUT, CIN, 3, 3]
    const float* bias_p   = (const float*)d_in[7];  // [NF, COUT]
    float* out = (float*)d_out;

    const int conv_elems = B_ * COUT_ * HW_ * HW_;        // 8388608
    const int attn_elems = B_ * NF_;                       // 256
    int write_attn = (out_size >= conv_elems + attn_elems) ? 1 : 0;
    float* attn_out = write_attn ? (out + conv_elems) : out;

    fc1_kernel<<<dim3(B_, 8), 256>>>(fc_in, fc1_w, fc1_b);
    fc2_kernel<<<B_, 256>>>(fc2_w, fc2_b, attn_out, write_attn);
    agg_kernel<<<dim3(36, B_), 256>>>(weight);

    const size_t smem_bytes = (size_t)SMEM_FLOATS * sizeof(float);  // 64512
    cudaFuncSetAttribute(conv_kernel, cudaFuncAttributeMaxDynamicSharedMemorySize,
                         (int)smem_bytes);
    conv_kernel<<<dim3(16, B_), 256, smem_bytes>>>(model_in, bias_p, out);
}

// round 16
// speedup vs baseline: 2.5440x; 1.4235x over previous
#include <cuda_runtime.h>
#include <cuda_bf16.h>
#include <cstdint>

// Shapes (fixed by the problem)
#define B_   32
#define D_   512
#define HID_ 256
#define NF_  8
#define CIN_ 64
#define COUT_ 64
#define HW_  64

// Conv tiling: CTA = 1 sample x (32w x 8h px) x all 64 oc. 256 thr, 2 CTAs/SM.
#define CC_    8                 // ci per chunk
#define NCH_   (CIN_ / CC_)      // 8
#define IROW_  36                // input smem row stride (34 used)
#define IPL_   (10 * IROW_)      // ci plane stride = 360 (=8 mod 32 -> conflict-free)
#define WBLK_  20                // smem floats per (tap,lane) weight block (16 used)

#define WBUF_  (9 * 32 * WBLK_)    // 5760 floats per W buffer
#define IBUF_  (CC_ * IPL_)        // 2880 floats per I buffer
#define SMEM_FLOATS (2 * WBUF_ + 2 * IBUF_)   // 17280 -> 69120 B

// -------- device scratch (no allocations allowed) --------
__device__ float g_attn[B_ * NF_];
__device__ float g_h[B_ * HID_];
// per-lane swizzled tf32 weights: [b][ch8][tap9][lane32][16]
__device__ float g_aggw2[B_ * 8 * 9 * 32 * 16];
// tf32-pre-rounded input copy
__device__ float g_xr[B_ * CIN_ * HW_ * HW_];

// -------- helpers --------
__device__ __forceinline__ float tf32r(float x) {
    uint32_t u;
    asm("cvt.rna.tf32.f32 %0, %1;" : "=r"(u) : "f"(x));
    return __uint_as_float(u);
}

__device__ __forceinline__ void mma8(float4& d,
                                     float a0, float a1, float a2, float a3,
                                     float b0, float b1) {
    asm("mma.sync.aligned.m16n8k8.row.col.f32.tf32.tf32.f32 "
        "{%0,%1,%2,%3},{%4,%5,%6,%7},{%8,%9},{%0,%1,%2,%3};"
        : "+f"(d.x), "+f"(d.y), "+f"(d.z), "+f"(d.w)
        : "r"(__float_as_uint(a0)), "r"(__float_as_uint(a1)),
          "r"(__float_as_uint(a2)), "r"(__float_as_uint(a3)),
          "r"(__float_as_uint(b0)), "r"(__float_as_uint(b1)));
}

__device__ __forceinline__ void cpa16(uint32_t dsh, const float* src) {
    asm volatile("cp.async.cg.shared.global [%0], [%1], 16;"
                 :: "r"(dsh), "l"(src));
}
__device__ __forceinline__ void cpa4z(uint32_t dsh, const float* src, int sz) {
    asm volatile("cp.async.ca.shared.global [%0], [%1], 4, %2;"
                 :: "r"(dsh), "l"(src), "r"(sz));
}
__device__ __forceinline__ void cpa_commit() {
    asm volatile("cp.async.commit_group;");
}
__device__ __forceinline__ void cpa_wait0() {
    asm volatile("cp.async.wait_group 0;");
}

// ============================================================
// Kernel 0: pre-round model input to tf32 (rna). grid(8192), block 256.
// ============================================================
__global__ void xround_kernel(const float* __restrict__ x)
{
    int i = blockIdx.x * blockDim.x + threadIdx.x;   // float4 index
    float4 v = reinterpret_cast<const float4*>(x)[i];
    v.x = tf32r(v.x); v.y = tf32r(v.y); v.z = tf32r(v.z); v.w = tf32r(v.w);
    reinterpret_cast<float4*>(g_xr)[i] = v;
}

// ============================================================
// Kernel 1a: fc1 -> relu -> g_h.   grid(32, 8), block 256.
// ============================================================
__global__ void fc1_kernel(const float* __restrict__ x,
                           const float* __restrict__ w1, const float* __restrict__ b1)
{
    const int b = blockIdx.x, s = blockIdx.y, t = threadIdx.x;
    __shared__ __align__(16) float xs[D_];
    for (int i = t; i < D_; i += 256) xs[i] = x[b * D_ + i];
    __syncthreads();

    const int u = s * 32 + (t >> 3);
    const int l8 = t & 7;
    const float4* wr = reinterpret_cast<const float4*>(w1 + (size_t)u * D_);
    const float4* xv = reinterpret_cast<const float4*>(xs);
    float acc = 0.f;
#pragma unroll
    for (int i = 0; i < 16; i++) {
        float4 w4 = wr[l8 + 8 * i], x4 = xv[l8 + 8 * i];
        acc += w4.x * x4.x + w4.y * x4.y + w4.z * x4.z + w4.w * x4.w;
    }
#pragma unroll
    for (int o = 4; o > 0; o >>= 1) acc += __shfl_xor_sync(0xffffffffu, acc, o);
    if (l8 == 0) g_h[b * HID_ + u] = fmaxf(acc + b1[u], 0.f);
}

// ============================================================
// Kernel 1b: fc2 + softmax -> g_attn (+ tuple tail of d_out). grid(32), block 256.
// ============================================================
__global__ void fc2_kernel(const float* __restrict__ w2, const float* __restrict__ b2,
                           float* __restrict__ attn_out, int write_out)
{
    const int b = blockIdx.x, t = threadIdx.x;
    __shared__ float hs[HID_];
    __shared__ float ls[NF_];
    __shared__ float as_[NF_];
    hs[t] = g_h[b * HID_ + t];
    __syncthreads();

    const int f = t >> 5, lane = t & 31;
    float s = 0.f;
#pragma unroll
    for (int i = 0; i < HID_ / 32; i++) s += hs[lane + 32 * i] * w2[f * HID_ + lane + 32 * i];
#pragma unroll
    for (int o = 16; o > 0; o >>= 1) s += __shfl_xor_sync(0xffffffffu, s, o);
    if (lane == 0) ls[f] = s + b2[f];
    __syncthreads();

    if (t == 0) {
        float m = -1e30f;
#pragma unroll
        for (int i = 0; i < NF_; i++) m = fmaxf(m, ls[i]);
        float Z = 0.f, e[NF_];
#pragma unroll
        for (int i = 0; i < NF_; i++) { e[i] = expf((ls[i] - m) * (1.0f / 30.0f)); Z += e[i]; }
#pragma unroll
        for (int i = 0; i < NF_; i++) as_[i] = e[i] / Z;
    }
    __syncthreads();
    if (t < NF_) {
        g_attn[b * NF_ + t] = as_[t];
        if (write_out) attn_out[b * NF_ + t] = as_[t];
    }
}

// ============================================================
// Kernel 2: agg_w -> per-lane swizzled [b][ch][tap][lane][16], tf32-rounded.
// grid(36, 32), block 256; reads weight [f][oc][ci][tap] coalesced (float4).
// lane = nl*4+kl (nl=oc&7, kl=ci&3), off = h*8+j (h=(ci&7)>>2, j=oc>>3).
// ============================================================
__global__ void agg_kernel(const float* __restrict__ weight)
{
    const int b = blockIdx.y;
    const int e = blockIdx.x * blockDim.x + threadIdx.x;  // float4 idx < 9216
    __shared__ float a[NF_];
    if (threadIdx.x < NF_) a[threadIdx.x] = g_attn[b * NF_ + threadIdx.x];
    __syncthreads();

    const float4* W = reinterpret_cast<const float4*>(weight);
    float4 acc = make_float4(0.f, 0.f, 0.f, 0.f);
#pragma unroll
    for (int f = 0; f < NF_; f++) {
        float4 w = W[(size_t)f * 9216 + e];
        float af = a[f];
        acc.x += af * w.x; acc.y += af * w.y; acc.z += af * w.z; acc.w += af * w.w;
    }
    float v[4] = { acc.x, acc.y, acc.z, acc.w };
    float* dst = g_aggw2 + (size_t)b * (8 * 9 * 32 * 16);
#pragma unroll
    for (int r = 0; r < 4; r++) {
        int idx = 4 * e + r;                 // oc*576 + ci*9 + tap
        int oc  = idx / 576;
        int rem = idx - oc * 576;
        int ci  = rem / 9;
        int tap = rem - ci * 9;
        int ch  = ci >> 3, rr = ci & 7;
        int kl  = rr & 3,  h  = rr >> 2;
        int nl  = oc & 7,  j  = oc >> 3;
        int lane = nl * 4 + kl;
        dst[(((ch * 9 + tap) * 32) + lane) * 16 + h * 8 + j] = tf32r(v[r]);
    }
}

// ============================================================
// Kernel 3: tf32 tensor-core conv (9 shifted GEMMs), cp.async double-buffered.
// grid(16 tiles[32x8], 32 b), block 256 (8 warps), 2 CTAs/SM.
// warp w = spatial row w (2 m16 px-tiles), all 64 oc (8 n-tiles).
// ============================================================
__global__ void __launch_bounds__(256, 2)
conv_kernel(const float* __restrict__ bias_p, float* __restrict__ out)
{
    extern __shared__ float smem[];
    float* wb[2] = { smem, smem + WBUF_ };
    float* ib[2] = { smem + 2 * WBUF_, smem + 2 * WBUF_ + IBUF_ };
    const uint32_t sbase = (uint32_t)__cvta_generic_to_shared(smem);
    const uint32_t wsh[2] = { sbase, sbase + WBUF_ * 4 };
    const uint32_t ish[2] = { sbase + 2 * WBUF_ * 4, sbase + (2 * WBUF_ + IBUF_) * 4 };

    const int b    = blockIdx.y;
    const int tile = blockIdx.x;               // 0..15
    const int tile_y = (tile >> 1) * 8;
    const int tile_x = (tile & 1) * 32;
    const int t    = threadIdx.x;
    const int w    = t >> 5;                   // warp id = spatial row 0..7
    const int lane = t & 31;
    const int kl   = lane & 3;                 // k-lane (ci)
    const int nl   = lane >> 2;                // n/m lane

    const float* xr = g_xr + (size_t)b * CIN_ * HW_ * HW_;
    const float* gw = g_aggw2 + (size_t)b * (8 * 9 * 32 * 16);

    // ---- async stagers ----
    auto stage = [&](int ch, int bufsel) {
        // weights: 1152 x 16B, per-lane blocks (compact src 16, padded dst 20)
        const float* wsrc = gw + (size_t)ch * (9 * 32 * 16);
        for (int idx = t; idx < 1152; idx += 256) {
            int q  = idx & 3;
            int bl = idx >> 2;                 // tap*32 + lane
            cpa16(wsh[bufsel] + (uint32_t)(bl * WBLK_ + 4 * q) * 4,
                  wsrc + bl * 16 + 4 * q);
        }
        // input: 2720 x 4B with zero-fill halo
        const int cb = ch * CC_;
        for (int idx = t; idx < CC_ * 10 * 34; idx += 256) {
            int ci  = idx / 340;
            int rem = idx - ci * 340;
            int r = rem / 34;
            int c = rem - r * 34;
            int gy = tile_y - 1 + r, gx = tile_x - 1 + c;
            bool in = ((unsigned)gy < (unsigned)HW_) && ((unsigned)gx < (unsigned)HW_);
            const float* s = in ? (xr + (size_t)(cb + ci) * (HW_ * HW_) + gy * HW_ + gx)
                                : xr;          // valid dummy when masked
            cpa4z(ish[bufsel] + (uint32_t)(ci * IPL_ + r * IROW_ + c) * 4, s, in ? 4 : 0);
        }
        cpa_commit();
    };

    float4 acc[2][8];                          // [m-tile][n-tile(oc/8)]
#pragma unroll
    for (int m = 0; m < 2; m++)
#pragma unroll
        for (int j = 0; j < 8; j++) acc[m][j] = make_float4(0.f, 0.f, 0.f, 0.f);

    stage(0, 0);
    cpa_wait0();
    __syncthreads();

    for (int ch = 0; ch < NCH_; ch++) {
        const int cur = ch & 1;
        if (ch + 1 < NCH_) stage(ch + 1, 1 - cur);   // async, overlapped with MMAs

        const float* I = ib[cur];
        const float* W = wb[cur];

#pragma unroll
        for (int tap = 0; tap < 9; tap++) {
            const int dy = tap / 3, dx = tap - 3 * (tap / 3);
            // A frags: scalar LDS, conflict-free (banks 8*kl + nl)
            const float* Ip = I + kl * IPL_ + (w + dy) * IROW_ + dx + nl;
            const float a00 = Ip[0],  a01 = Ip[8];
            const float a10 = Ip[16], a11 = Ip[24];
            const float a02 = Ip[4 * IPL_],      a03 = Ip[4 * IPL_ + 8];
            const float a12 = Ip[4 * IPL_ + 16], a13 = Ip[4 * IPL_ + 24];
            // B frags: 4 conflict-free LDS.128 from this lane's block
            const float4* Bp = reinterpret_cast<const float4*>(
                W + (tap * 32 + lane) * WBLK_);
            const float4 v0 = Bp[0], v1 = Bp[1], v2 = Bp[2], v3 = Bp[3];
            const float b0a[8] = { v0.x, v0.y, v0.z, v0.w, v1.x, v1.y, v1.z, v1.w };
            const float b1a[8] = { v2.x, v2.y, v2.z, v2.w, v3.x, v3.y, v3.z, v3.w };
#pragma unroll
            for (int j = 0; j < 8; j++) {
                mma8(acc[0][j], a00, a01, a02, a03, b0a[j], b1a[j]);
                mma8(acc[1][j], a10, a11, a12, a13, b0a[j], b1a[j]);
            }
        }
        if (ch + 1 < NCH_) cpa_wait0();
        __syncthreads();
    }

    // epilogue: dynamic bias (smem reuse after final barrier)
    float* bias_s = smem;
    if (t < COUT_) {
        float bs = 0.f;
#pragma unroll
        for (int f = 0; f < NF_; f++) bs += g_attn[b * NF_ + f] * bias_p[f * COUT_ + t];
        bias_s[t] = bs;
    }
    __syncthreads();

    const int gy = tile_y + w;
#pragma unroll
    for (int mt = 0; mt < 2; mt++) {
        const int gxa = tile_x + mt * 16 + nl;
        const int gxb = gxa + 8;
#pragma unroll
        for (int j = 0; j < 8; j++) {
            const int oc0 = 8 * j + 2 * kl;
            const int oc1 = oc0 + 1;
            const float bs0 = bias_s[oc0], bs1 = bias_s[oc1];
            float* p0 = out + (((size_t)b * COUT_ + oc0) * HW_ + gy) * HW_;
            float* p1 = out + (((size_t)b * COUT_ + oc1) * HW_ + gy) * HW_;
            p0[gxa] = acc[mt][j].x + bs0;
            p1[gxa] = acc[mt][j].y + bs1;
            p0[gxb] = acc[mt][j].z + bs0;
            p1[gxb] = acc[mt][j].w + bs1;
        }
    }
}

// ============================================================
extern "C" void kernel_launch(void* const* d_in, const int* in_sizes, int n_in,
                              void* d_out, int out_size)
{
    const float* fc_in    = (const float*)d_in[0];  // [B, D]
    const float* model_in = (const float*)d_in[1];  // [B, CIN, HW, HW]
    const float* fc1_w    = (const float*)d_in[2];  // [HID, D]
    const float* fc1_b    = (const float*)d_in[3];  // [HID]
    const float* fc2_w    = (const float*)d_in[4];  // [NF, HID]
    const float* fc2_b    = (const float*)d_in[5];  // [NF]
    const float* weight   = (const float*)d_in[6];  // [NF, COUT, CIN, 3, 3]
    const float* bias_p   = (const float*)d_in[7];  // [NF, COUT]
    float* out = (float*)d_out;

    const int conv_elems = B_ * COUT_ * HW_ * HW_;        // 8388608
    const int attn_elems = B_ * NF_;                       // 256
    int write_attn = (out_size >= conv_elems + attn_elems) ? 1 : 0;
    float* attn_out = write_attn ? (out + conv_elems) : out;

    xround_kernel<<<conv_elems / 4 / 256, 256>>>(model_in);
    fc1_kernel<<<dim3(B_, 8), 256>>>(fc_in, fc1_w, fc1_b);
    fc2_kernel<<<B_, 256>>>(fc2_w, fc2_b, attn_out, write_attn);
    agg_kernel<<<dim3(36, B_), 256>>>(weight);

    const size_t smem_bytes = (size_t)SMEM_FLOATS * sizeof(float);  // 69120
    cudaFuncSetAttribute(conv_kernel, cudaFuncAttributeMaxDynamicSharedMemorySize,
                         (int)smem_bytes);
    conv_kernel<<<dim3(16, B_), 256, smem_bytes>>>(bias_p, out);
}